// round 14
// baseline (speedup 1.0000x reference)
#include <cuda_runtime.h>
#include <cstdint>

#define NVOX   200000
#define NP     100000
#define KK     27
#define CCH    64
#define TP     256                        // pairs per block (GEMM M)
#define NTHR   512
#define NBLK   ((NP + TP - 1) / TP)       // 391
#define XPAD   68                         // X/W tile row stride (floats)
#define SPAD   80                         // stage row stride (floats)

// smem layout (bytes):
#define SM_SIN  0                                  // int[256]
#define SM_SOUT 1024                               // int[256]
#define SM_X    2048                               // [256][68] f32 = 69632
#define SM_W    (2048 + 69632)                     // [64][68]  f32 = 17408
#define SM_STAGE SM_X                              // [256][80] f32 = 81920 (reuse X+W)
#define SMEM_TOTAL (2048 + 69632 + 17408)          // 89088

__device__ float g_stats[2 * CCH];       // BN sum / sumsq
__device__ float g_wt[KK * CCH * CCH];   // W^T [k][outc][inc], tf32 (rna) bits

__device__ __forceinline__ uint32_t f2tf32(float f) {
    uint32_t r;
    asm("cvt.rna.tf32.f32 %0, %1;" : "=r"(r) : "f"(f));
    return r;
}
__device__ __forceinline__ uint32_t smem_u32(const void* p) {
    uint32_t a;
    asm("{ .reg .u64 t; cvta.to.shared.u64 t, %1; cvt.u32.u64 %0, t; }" : "=r"(a) : "l"(p));
    return a;
}
__device__ __forceinline__ void cpasync16(uint32_t sdst, const void* gsrc) {
    asm volatile("cp.async.cg.shared.global [%0], [%1], 16;"
                 :: "r"(sdst), "l"(__cvta_generic_to_global(gsrc)) : "memory");
}
__device__ __forceinline__ void mma_tf32(float* d, const uint32_t* a, const uint32_t* b) {
    asm volatile(
        "mma.sync.aligned.m16n8k8.row.col.f32.tf32.tf32.f32 "
        "{%0,%1,%2,%3}, {%4,%5,%6,%7}, {%8,%9}, {%0,%1,%2,%3};"
        : "+f"(d[0]), "+f"(d[1]), "+f"(d[2]), "+f"(d[3])
        : "r"(a[0]), "r"(a[1]), "r"(a[2]), "r"(a[3]), "r"(b[0]), "r"(b[1]));
}
__device__ __forceinline__ void bulk_red_add_row(float* gdst, uint32_t ssrc) {
    asm volatile(
        "cp.reduce.async.bulk.global.shared::cta.bulk_group.add.f32 [%0], [%1], 256;"
        :: "l"(__cvta_generic_to_global(gdst)), "r"(ssrc) : "memory");
}

// ---------------------------------------------------------------------------
// prep: zero BN stats; transpose W[k][in][out] -> g_wt[k][out][in] (tf32 rna)
// ---------------------------------------------------------------------------
__global__ __launch_bounds__(256) void prep_kernel(const float* __restrict__ w) {
    const int k = blockIdx.x;
    const int tid = threadIdx.x;
    if (k == 0 && tid < 2 * CCH) g_stats[tid] = 0.0f;
    const float* wk = w + (size_t)k * CCH * CCH;
    uint32_t* dst = (uint32_t*)(g_wt + (size_t)k * CCH * CCH);
    #pragma unroll
    for (int it = 0; it < 16; ++it) {
        int j = tid + it * 256;          // j = n*64 + i
        int n = j >> 6, i = j & 63;
        dst[j] = f2tf32(wk[i * CCH + n]);
    }
}

// ---------------------------------------------------------------------------
// conv: block = (256-pair tile, k), 512 threads. cp.async gather (raw fp32;
// HMMA truncates to tf32), tf32 mma.sync GEMM (warp w: rows (w&7)*32,
// cols (w>>3)*32), staged TMA bulk-reduce scatter. Structure == R8, tile 2x.
// ---------------------------------------------------------------------------
__global__ __launch_bounds__(NTHR) void conv_kernel(
    const float* __restrict__ x,
    const int*   __restrict__ kin,
    const int*   __restrict__ kout,
    float*       __restrict__ out)
{
    extern __shared__ char smem[];
    int*      sIn  = (int*)(smem + SM_SIN);
    int*      sOut = (int*)(smem + SM_SOUT);
    uint32_t* Xsh  = (uint32_t*)(smem + SM_X);    // [256][XPAD]
    uint32_t* Wsh  = (uint32_t*)(smem + SM_W);    // [64][XPAD]
    float*    Sst  = (float*)(smem + SM_STAGE);   // [256][SPAD] (post-GEMM reuse)

    const int tid  = threadIdx.x;
    const int warp = tid >> 5;
    const int lane = tid & 31;
    const int k     = blockIdx.y;
    const int pbase = blockIdx.x * TP;

    if (tid < TP) {
        int p = pbase + tid;
        bool v = (p < NP);
        sIn[tid]  = v ? kin[(size_t)k * NP + p]  : -1;
        sOut[tid] = v ? kout[(size_t)k * NP + p] : 0;
    }
    __syncthreads();

    // ---- gather A rows via cp.async: 16 threads per row, 8 iterations ----
    const uint32_t sbX = smem_u32(Xsh);
    #pragma unroll
    for (int it = 0; it < 8; ++it) {
        int idx   = tid + it * NTHR;     // 0..4095
        int row   = idx >> 4;            // 0..255
        int chunk = idx & 15;
        int in    = sIn[row];
        uint32_t dst = sbX + (row * XPAD + chunk * 4) * 4;
        if (in >= 0) {
            cpasync16(dst, x + (size_t)in * CCH + chunk * 4);
        } else {
            *(uint4*)(smem + SM_X + (row * XPAD + chunk * 4) * 4) = make_uint4(0, 0, 0, 0);
        }
    }
    // ---- W^T[k] tile via cp.async: 64 rows x 16 chunks ----
    {
        const uint32_t sbW = smem_u32(Wsh);
        const float* src = g_wt + (size_t)k * CCH * CCH;
        #pragma unroll
        for (int r = 0; r < 2; ++r) {
            int idx = tid + r * NTHR;    // 0..1023
            int row = idx >> 4;
            int jj  = idx & 15;
            cpasync16(sbW + (row * XPAD + jj * 4) * 4, src + row * CCH + jj * 4);
        }
    }
    asm volatile("cp.async.commit_group;" ::: "memory");
    asm volatile("cp.async.wait_group 0;" ::: "memory");
    __syncthreads();

    // ---- warp GEMM: 2 mtiles x 4 ntiles x 8 ktiles of m16n8k8 ----
    const int m0 = (warp & 7) * 32;
    const int n0 = (warp >> 3) * 32;
    const int g  = lane >> 2;
    const int t4 = lane & 3;

    float acc[2][4][4];
    #pragma unroll
    for (int mt = 0; mt < 2; ++mt)
        #pragma unroll
        for (int nt = 0; nt < 4; ++nt)
            #pragma unroll
            for (int e = 0; e < 4; ++e) acc[mt][nt][e] = 0.0f;

    #pragma unroll
    for (int kt = 0; kt < 8; ++kt) {
        const int kc = kt * 8 + t4;
        uint32_t a[2][4];
        #pragma unroll
        for (int mt = 0; mt < 2; ++mt) {
            const uint32_t* base = Xsh + (m0 + mt * 16 + g) * XPAD + kc;
            a[mt][0] = base[0];
            a[mt][1] = base[8 * XPAD];
            a[mt][2] = base[4];
            a[mt][3] = base[8 * XPAD + 4];
        }
        uint32_t b[4][2];
        #pragma unroll
        for (int nt = 0; nt < 4; ++nt) {
            const uint32_t* base = Wsh + (n0 + nt * 8 + g) * XPAD + kc;
            b[nt][0] = base[0];
            b[nt][1] = base[4];
        }
        #pragma unroll
        for (int mt = 0; mt < 2; ++mt)
            #pragma unroll
            for (int nt = 0; nt < 4; ++nt)
                mma_tf32(acc[mt][nt], a[mt], b[nt]);
    }

    // ---- all LDS of X/W done; stage region reuses their smem ----
    __syncthreads();

    // ---- stage: shuffle-pack 4 contiguous cols, STS.128 into Sst ----
    const bool evenl = (lane & 1) == 0;
    const int  cb0   = n0 + (t4 >> 1) * 4;
    #pragma unroll
    for (int mt = 0; mt < 2; ++mt) {
        #pragma unroll
        for (int nt = 0; nt < 4; ++nt) {
            float c0 = acc[mt][nt][0], c1 = acc[mt][nt][1];
            float c2 = acc[mt][nt][2], c3 = acc[mt][nt][3];
            float s0 = __shfl_xor_sync(0xffffffffu, c0, 1);
            float s1 = __shfl_xor_sync(0xffffffffu, c1, 1);
            float s2 = __shfl_xor_sync(0xffffffffu, c2, 1);
            float s3 = __shfl_xor_sync(0xffffffffu, c3, 1);
            float4 v;
            int    mrow;
            if (evenl) {
                v = make_float4(c0, c1, s0, s1);
                mrow = m0 + mt * 16 + g;
            } else {
                v = make_float4(s2, s3, c2, c3);
                mrow = m0 + mt * 16 + g + 8;
            }
            *(float4*)(Sst + mrow * SPAD + cb0 + nt * 8) = v;
        }
    }
    __syncthreads();

    // ---- TMA bulk reduce-add: one 256B row per thread (threads 0..255) ----
    if (tid < TP) {
        asm volatile("fence.proxy.async.shared::cta;" ::: "memory");
        int o = sOut[tid];
        uint32_t ssrc = smem_u32(Sst + tid * SPAD);
        bulk_red_add_row(out + (size_t)o * CCH, ssrc);
        asm volatile("cp.async.bulk.commit_group;" ::: "memory");
        asm volatile("cp.async.bulk.wait_group 0;" ::: "memory");
    }
}

// ---------------------------------------------------------------------------
// BN stats + fused normalize (unchanged)
// ---------------------------------------------------------------------------
__global__ __launch_bounds__(256) void stats_kernel(const float* __restrict__ y) {
    __shared__ float4 shs[256];
    __shared__ float4 shq[256];
    const int tid = threadIdx.x;
    const int cg  = tid & 15;
    const int r0  = tid >> 4;
    float4 s = make_float4(0.f, 0.f, 0.f, 0.f);
    float4 q = make_float4(0.f, 0.f, 0.f, 0.f);
    const float4* y4 = (const float4*)y;
    for (int row = blockIdx.x * 16 + r0; row < NVOX; row += gridDim.x * 16) {
        float4 v = y4[row * 16 + cg];
        s.x += v.x; s.y += v.y; s.z += v.z; s.w += v.w;
        q.x += v.x * v.x; q.y += v.y * v.y; q.z += v.z * v.z; q.w += v.w * v.w;
    }
    shs[tid] = s; shq[tid] = q;
    __syncthreads();
    #pragma unroll
    for (int off = 128; off >= 16; off >>= 1) {
        if (tid < off) {
            float4 a = shs[tid], b = shs[tid + off];
            a.x += b.x; a.y += b.y; a.z += b.z; a.w += b.w; shs[tid] = a;
            float4 c = shq[tid], d = shq[tid + off];
            c.x += d.x; c.y += d.y; c.z += d.z; c.w += d.w; shq[tid] = c;
        }
        __syncthreads();
    }
    if (tid < 16) {
        float4 a = shs[tid], c = shq[tid];
        int col = tid * 4;
        atomicAdd(&g_stats[col + 0], a.x);
        atomicAdd(&g_stats[col + 1], a.y);
        atomicAdd(&g_stats[col + 2], a.z);
        atomicAdd(&g_stats[col + 3], a.w);
        atomicAdd(&g_stats[CCH + col + 0], c.x);
        atomicAdd(&g_stats[CCH + col + 1], c.y);
        atomicAdd(&g_stats[CCH + col + 2], c.z);
        atomicAdd(&g_stats[CCH + col + 3], c.w);
    }
}

__global__ __launch_bounds__(256) void norm_kernel(
    float* __restrict__ y, const float* __restrict__ gamma, const float* __restrict__ beta)
{
    __shared__ float sc[CCH];
    __shared__ float bi[CCH];
    const int tid = threadIdx.x;
    if (tid < CCH) {
        const float invN = 1.0f / (float)NVOX;
        float mean = g_stats[tid] * invN;
        float var  = g_stats[CCH + tid] * invN - mean * mean;
        float s = rsqrtf(var + 1e-5f) * gamma[tid];
        sc[tid] = s;
        bi[tid] = beta[tid] - mean * s;
    }
    __syncthreads();
    const int total4 = NVOX * 16;
    float4* y4 = (float4*)y;
    for (int idx = blockIdx.x * 256 + tid; idx < total4; idx += gridDim.x * 256) {
        int c = (idx & 15) * 4;
        float4 v = y4[idx];
        v.x = fmaxf(fmaf(v.x, sc[c + 0], bi[c + 0]), 0.f);
        v.y = fmaxf(fmaf(v.y, sc[c + 1], bi[c + 1]), 0.f);
        v.z = fmaxf(fmaf(v.z, sc[c + 2], bi[c + 2]), 0.f);
        v.w = fmaxf(fmaf(v.w, sc[c + 3], bi[c + 3]), 0.f);
        y4[idx] = v;
    }
}

// ---------------------------------------------------------------------------
extern "C" void kernel_launch(void* const* d_in, const int* in_sizes, int n_in,
                              void* d_out, int out_size) {
    const float* x     = (const float*)d_in[0];
    const float* w     = (const float*)d_in[1];
    const float* gamma = (const float*)d_in[2];
    const float* beta  = (const float*)d_in[3];
    const int*   kin   = (const int*)d_in[4];
    const int*   kout  = (const int*)d_in[5];
    float*       out   = (float*)d_out;

    cudaFuncSetAttribute(conv_kernel, cudaFuncAttributeMaxDynamicSharedMemorySize, SMEM_TOTAL);

    cudaMemsetAsync(out, 0, (size_t)NVOX * CCH * sizeof(float), 0);
    prep_kernel<<<KK, 256>>>(w);
    conv_kernel<<<dim3(NBLK, KK), NTHR, SMEM_TOTAL>>>(x, kin, kout, out);
    stats_kernel<<<512, 256>>>(out);
    norm_kernel<<<2048, 256>>>(out, gamma, beta);
}

// round 15
// speedup vs baseline: 1.2681x; 1.2681x over previous
#include <cuda_runtime.h>
#include <cstdint>

#define NVOX   200000
#define NP     100000
#define KK     27
#define CCH    64
#define TP     128                        // pairs per block (GEMM M)
#define NBLK   ((NP + TP - 1) / TP)       // 782
#define XPAD   68                         // padded row stride (floats) for X/W tiles
#define SPAD   80                         // stage row stride (floats)
#define NZB    832                        // zeroing blocks appended to prep grid
#define FNB    296                        // finalize blocks (resident-safe grid barrier)

// smem layout (bytes) for conv:
#define SM_SIN  0
#define SM_SOUT 512
#define SM_X    1024                              // X tile [128][68] f32 (34816 B)
#define SM_W    (1024 + 34816)                    // W tile [64][68] f32  (17408 B)
#define SM_STAGE SM_X                             // stage [128][80] reuses X+W after GEMM
#define SMEM_TOTAL (1024 + 34816 + 17408)         // 53248

__device__ float        g_stats[2 * CCH];  // BN sum / sumsq
__device__ unsigned int g_ctr;             // grid-barrier counter (reset in prep)
__device__ float        g_wt[KK * CCH * CCH];   // W^T [k][outc][inc], tf32 (rna) bits

__device__ __forceinline__ uint32_t f2tf32(float f) {
    uint32_t r;
    asm("cvt.rna.tf32.f32 %0, %1;" : "=r"(r) : "f"(f));
    return r;
}
__device__ __forceinline__ uint32_t smem_u32(const void* p) {
    uint32_t a;
    asm("{ .reg .u64 t; cvta.to.shared.u64 t, %1; cvt.u32.u64 %0, t; }" : "=r"(a) : "l"(p));
    return a;
}
__device__ __forceinline__ void cpasync16(uint32_t sdst, const void* gsrc) {
    asm volatile("cp.async.cg.shared.global [%0], [%1], 16;"
                 :: "r"(sdst), "l"(__cvta_generic_to_global(gsrc)) : "memory");
}
__device__ __forceinline__ void mma_tf32(float* d, const uint32_t* a, const uint32_t* b) {
    asm volatile(
        "mma.sync.aligned.m16n8k8.row.col.f32.tf32.tf32.f32 "
        "{%0,%1,%2,%3}, {%4,%5,%6,%7}, {%8,%9}, {%0,%1,%2,%3};"
        : "+f"(d[0]), "+f"(d[1]), "+f"(d[2]), "+f"(d[3])
        : "r"(a[0]), "r"(a[1]), "r"(a[2]), "r"(a[3]), "r"(b[0]), "r"(b[1]));
}
__device__ __forceinline__ void bulk_red_add_row(float* gdst, uint32_t ssrc) {
    asm volatile(
        "cp.reduce.async.bulk.global.shared::cta.bulk_group.add.f32 [%0], [%1], 256;"
        :: "l"(__cvta_generic_to_global(gdst)), "r"(ssrc) : "memory");
}

// ---------------------------------------------------------------------------
// prep: blocks 0..KK-1 transpose W (tf32 rna) + reset stats/counter;
//       blocks KK.. zero the output accumulator (replaces cudaMemsetAsync).
// ---------------------------------------------------------------------------
__global__ __launch_bounds__(256) void prep_kernel(const float* __restrict__ w,
                                                   float* __restrict__ out) {
    const int b   = blockIdx.x;
    const int tid = threadIdx.x;
    if (b < KK) {
        if (b == 0) {
            if (tid < 2 * CCH) g_stats[tid] = 0.0f;
            if (tid == 0) g_ctr = 0u;
        }
        const float* wk = w + (size_t)b * CCH * CCH;
        uint32_t* dst = (uint32_t*)(g_wt + (size_t)b * CCH * CCH);
        #pragma unroll
        for (int it = 0; it < 16; ++it) {
            int j = tid + it * 256;          // j = n*64 + i
            int n = j >> 6, i = j & 63;
            dst[j] = f2tf32(wk[i * CCH + n]);
        }
    } else {
        const int     zb    = b - KK;        // 0..NZB-1
        const int     total = NVOX * CCH / 4;   // 3.2M uint4
        uint4*        o4    = (uint4*)out;
        const uint4   z     = make_uint4(0, 0, 0, 0);
        for (int i = zb * 256 + tid; i < total; i += NZB * 256) o4[i] = z;
    }
}

// ---------------------------------------------------------------------------
// conv: byte-identical to R8 (proven 320us). Block = (128-pair tile, k).
// cp.async gather (raw fp32; HMMA truncates to tf32), tf32 mma.sync GEMM,
// staged TMA bulk-reduce scatter.
// ---------------------------------------------------------------------------
__global__ __launch_bounds__(256) void conv_kernel(
    const float* __restrict__ x,
    const int*   __restrict__ kin,
    const int*   __restrict__ kout,
    float*       __restrict__ out)
{
    extern __shared__ char smem[];
    int*      sIn  = (int*)(smem + SM_SIN);
    int*      sOut = (int*)(smem + SM_SOUT);
    uint32_t* Xsh  = (uint32_t*)(smem + SM_X);    // [128][XPAD]
    uint32_t* Wsh  = (uint32_t*)(smem + SM_W);    // [64][XPAD]
    float*    Sst  = (float*)(smem + SM_STAGE);   // [128][SPAD] (post-GEMM reuse)

    const int tid  = threadIdx.x;
    const int warp = tid >> 5;
    const int lane = tid & 31;
    const int k     = blockIdx.y;
    const int pbase = blockIdx.x * TP;

    if (tid < TP) {
        int p = pbase + tid;
        bool v = (p < NP);
        sIn[tid]  = v ? kin[(size_t)k * NP + p]  : -1;
        sOut[tid] = v ? kout[(size_t)k * NP + p] : 0;
    }
    __syncthreads();

    // ---- gather A rows via cp.async: 16 threads per row, 8 iterations ----
    const uint32_t sbX = smem_u32(Xsh);
    #pragma unroll
    for (int it = 0; it < 8; ++it) {
        int idx   = tid + it * 256;      // 0..2047
        int row   = idx >> 4;            // 0..127
        int chunk = idx & 15;            // 16B chunk within the 256B row
        int in    = sIn[row];
        uint32_t dst = sbX + (row * XPAD + chunk * 4) * 4;
        if (in >= 0) {
            cpasync16(dst, x + (size_t)in * CCH + chunk * 4);
        } else {
            *(uint4*)(smem + SM_X + (row * XPAD + chunk * 4) * 4) = make_uint4(0, 0, 0, 0);
        }
    }
    // ---- W^T[k] tile via cp.async: 64 rows x 16 chunks ----
    {
        const uint32_t sbW = smem_u32(Wsh);
        const float* src = g_wt + (size_t)k * CCH * CCH;
        #pragma unroll
        for (int r = 0; r < 4; ++r) {
            int idx = tid + r * 256;
            int row = idx >> 4;
            int jj  = idx & 15;
            cpasync16(sbW + (row * XPAD + jj * 4) * 4, src + row * CCH + jj * 4);
        }
    }
    asm volatile("cp.async.commit_group;" ::: "memory");
    asm volatile("cp.async.wait_group 0;" ::: "memory");
    __syncthreads();

    // ---- warp GEMM: 2 mtiles x 4 ntiles x 8 ktiles of m16n8k8 ----
    const int m0 = (warp & 3) * 32;
    const int n0 = (warp >> 2) * 32;
    const int g  = lane >> 2;
    const int t4 = lane & 3;

    float acc[2][4][4];
    #pragma unroll
    for (int mt = 0; mt < 2; ++mt)
        #pragma unroll
        for (int nt = 0; nt < 4; ++nt)
            #pragma unroll
            for (int e = 0; e < 4; ++e) acc[mt][nt][e] = 0.0f;

    #pragma unroll
    for (int kt = 0; kt < 8; ++kt) {
        const int kc = kt * 8 + t4;
        uint32_t a[2][4];
        #pragma unroll
        for (int mt = 0; mt < 2; ++mt) {
            const uint32_t* base = Xsh + (m0 + mt * 16 + g) * XPAD + kc;
            a[mt][0] = base[0];
            a[mt][1] = base[8 * XPAD];
            a[mt][2] = base[4];
            a[mt][3] = base[8 * XPAD + 4];
        }
        uint32_t b[4][2];
        #pragma unroll
        for (int nt = 0; nt < 4; ++nt) {
            const uint32_t* base = Wsh + (n0 + nt * 8 + g) * XPAD + kc;
            b[nt][0] = base[0];
            b[nt][1] = base[4];
        }
        #pragma unroll
        for (int mt = 0; mt < 2; ++mt)
            #pragma unroll
            for (int nt = 0; nt < 4; ++nt)
                mma_tf32(acc[mt][nt], a[mt], b[nt]);
    }

    // ---- all LDS of X/W done; stage region reuses their smem ----
    __syncthreads();

    // ---- stage: shuffle-pack 4 contiguous cols, STS.128 into Sst ----
    const bool evenl = (lane & 1) == 0;
    const int  cb0   = n0 + (t4 >> 1) * 4;
    #pragma unroll
    for (int mt = 0; mt < 2; ++mt) {
        #pragma unroll
        for (int nt = 0; nt < 4; ++nt) {
            float c0 = acc[mt][nt][0], c1 = acc[mt][nt][1];
            float c2 = acc[mt][nt][2], c3 = acc[mt][nt][3];
            float s0 = __shfl_xor_sync(0xffffffffu, c0, 1);
            float s1 = __shfl_xor_sync(0xffffffffu, c1, 1);
            float s2 = __shfl_xor_sync(0xffffffffu, c2, 1);
            float s3 = __shfl_xor_sync(0xffffffffu, c3, 1);
            float4 v;
            int    mrow;
            if (evenl) {
                v = make_float4(c0, c1, s0, s1);
                mrow = m0 + mt * 16 + g;
            } else {
                v = make_float4(s2, s3, c2, c3);
                mrow = m0 + mt * 16 + g + 8;
            }
            *(float4*)(Sst + mrow * SPAD + cb0 + nt * 8) = v;
        }
    }
    __syncthreads();

    // ---- TMA bulk reduce-add: one 256B row per thread (threads 0..127) ----
    if (tid < TP) {
        asm volatile("fence.proxy.async.shared::cta;" ::: "memory");
        int o = sOut[tid];
        uint32_t ssrc = smem_u32(Sst + tid * SPAD);
        bulk_red_add_row(out + (size_t)o * CCH, ssrc);
        asm volatile("cp.async.bulk.commit_group;" ::: "memory");
        asm volatile("cp.async.bulk.wait_group 0;" ::: "memory");
    }
}

// ---------------------------------------------------------------------------
// finalize: fused BN stats + normalize with a counter-based grid barrier.
// FNB=296 blocks of 256 threads (far below residency limit -> spin is safe).
// Phase A: grid-stride partial sums -> atomicAdd into g_stats.
// Barrier: threadfence + atomicAdd(g_ctr), spin until all FNB arrived.
// Phase B: compute scale/bias, grid-stride normalize + ReLU in place.
// ---------------------------------------------------------------------------
__global__ __launch_bounds__(256) void finalize_kernel(
    float* __restrict__ y, const float* __restrict__ gamma, const float* __restrict__ beta)
{
    __shared__ float4 shs[256];
    __shared__ float4 shq[256];
    __shared__ float  sc[CCH];
    __shared__ float  bi[CCH];

    const int tid = threadIdx.x;
    const int cg  = tid & 15;
    const int r0  = tid >> 4;

    // ---- Phase A: stats ----
    {
        float4 s = make_float4(0.f, 0.f, 0.f, 0.f);
        float4 q = make_float4(0.f, 0.f, 0.f, 0.f);
        const float4* y4 = (const float4*)y;
        for (int row = blockIdx.x * 16 + r0; row < NVOX; row += FNB * 16) {
            float4 v = y4[row * 16 + cg];
            s.x += v.x; s.y += v.y; s.z += v.z; s.w += v.w;
            q.x += v.x * v.x; q.y += v.y * v.y; q.z += v.z * v.z; q.w += v.w * v.w;
        }
        shs[tid] = s; shq[tid] = q;
        __syncthreads();
        #pragma unroll
        for (int off = 128; off >= 16; off >>= 1) {
            if (tid < off) {
                float4 a = shs[tid], b = shs[tid + off];
                a.x += b.x; a.y += b.y; a.z += b.z; a.w += b.w; shs[tid] = a;
                float4 c = shq[tid], d = shq[tid + off];
                c.x += d.x; c.y += d.y; c.z += d.z; c.w += d.w; shq[tid] = c;
            }
            __syncthreads();
        }
        if (tid < 16) {
            float4 a = shs[tid], c = shq[tid];
            int col = tid * 4;
            atomicAdd(&g_stats[col + 0], a.x);
            atomicAdd(&g_stats[col + 1], a.y);
            atomicAdd(&g_stats[col + 2], a.z);
            atomicAdd(&g_stats[col + 3], a.w);
            atomicAdd(&g_stats[CCH + col + 0], c.x);
            atomicAdd(&g_stats[CCH + col + 1], c.y);
            atomicAdd(&g_stats[CCH + col + 2], c.z);
            atomicAdd(&g_stats[CCH + col + 3], c.w);
        }
    }
    __syncthreads();

    // ---- grid barrier ----
    if (tid == 0) {
        __threadfence();
        atomicAdd(&g_ctr, 1u);
        while (*(volatile unsigned int*)&g_ctr < (unsigned int)FNB) { }
        __threadfence();
    }
    __syncthreads();

    // ---- Phase B: normalize + ReLU ----
    if (tid < CCH) {
        const float invN = 1.0f / (float)NVOX;
        float mean = g_stats[tid] * invN;
        float var  = g_stats[CCH + tid] * invN - mean * mean;
        float s = rsqrtf(var + 1e-5f) * gamma[tid];
        sc[tid] = s;
        bi[tid] = beta[tid] - mean * s;
    }
    __syncthreads();

    const int total4 = NVOX * 16;
    float4* y4 = (float4*)y;
    for (int idx = blockIdx.x * 256 + tid; idx < total4; idx += FNB * 256) {
        int c = (idx & 15) * 4;
        float4 v = y4[idx];
        v.x = fmaxf(fmaf(v.x, sc[c + 0], bi[c + 0]), 0.f);
        v.y = fmaxf(fmaf(v.y, sc[c + 1], bi[c + 1]), 0.f);
        v.z = fmaxf(fmaf(v.z, sc[c + 2], bi[c + 2]), 0.f);
        v.w = fmaxf(fmaf(v.w, sc[c + 3], bi[c + 3]), 0.f);
        y4[idx] = v;
    }
}

// ---------------------------------------------------------------------------
extern "C" void kernel_launch(void* const* d_in, const int* in_sizes, int n_in,
                              void* d_out, int out_size) {
    const float* x     = (const float*)d_in[0];
    const float* w     = (const float*)d_in[1];
    const float* gamma = (const float*)d_in[2];
    const float* beta  = (const float*)d_in[3];
    const int*   kin   = (const int*)d_in[4];
    const int*   kout  = (const int*)d_in[5];
    float*       out   = (float*)d_out;

    cudaFuncSetAttribute(conv_kernel, cudaFuncAttributeMaxDynamicSharedMemorySize, SMEM_TOTAL);

    prep_kernel<<<KK + NZB, 256>>>(w, out);                      // W^T + zero out + reset
    conv_kernel<<<dim3(NBLK, KK), 256, SMEM_TOTAL>>>(x, kin, kout, out);
    finalize_kernel<<<FNB, 256>>>(out, gamma, beta);             // stats + BN + ReLU
}